// round 12
// baseline (speedup 1.0000x reference)
#include <cuda_runtime.h>

// Problem constants (SUBDIVISIONS=7, BATCH=16)
#define BATCH 16
#define YDIM  640
#define XDIM  256
#define BH    128            // YDIM/5
#define YX    (YDIM*XDIM)    // 163840
#define NV    (YX + 2)       // 163842 vertices
#define BPT   16             // all batches in one thread: metadata/chain paid once

// Scratch (static __device__ — no allocation allowed)
__device__ float4 g_v4[BATCH * NV];   // padded xyz_ per batch (~42 MB)
__device__ int    g_cnt[NV];          // per-vertex ring fill counters
__device__ int2   g_ring[NV * 6];     // per-vertex opposite-edge pairs (a,b)
__device__ double g_acc;              // fused loss accumulator
__device__ unsigned int g_done;       // ticket counter for fused finalization

// ---------------------------------------------------------------------------
// K1: build v = [grid verts ; top pole ; bottom pole] as float4 (w unused).
// inputs layout: (B, 3, Y, X) row-major
// ---------------------------------------------------------------------------
__global__ void k_build_v(const float* __restrict__ inp) {
    int vtx = blockIdx.x * blockDim.x + threadIdx.x;
    int b   = blockIdx.y;
    if (vtx > YX + 1) return;
    const float* base = inp + (size_t)b * 3 * YX;
    float4 o;
    o.w = 0.0f;
    if (vtx < YX) {
        o.x = base[vtx];
        o.y = base[YX + vtx];
        o.z = base[2 * YX + vtx];
    } else if (vtx == YX) {
        float s[3];
        #pragma unroll
        for (int c = 0; c < 3; c++) {
            s[c] = 0.0f;
            #pragma unroll
            for (int i = 0; i < 5; i++) s[c] += base[c * YX + (i * BH) * XDIM];
            s[c] *= 0.2f;
        }
        o.x = s[0]; o.y = s[1]; o.z = s[2];
    } else {
        float s[3];
        #pragma unroll
        for (int c = 0; c < 3; c++) {
            s[c] = 0.0f;
            #pragma unroll
            for (int i = 1; i <= 5; i++)
                s[c] += base[c * YX + (i * BH - 1) * XDIM + (XDIM - 1)];
            s[c] *= 0.2f;
        }
        o.x = s[0]; o.y = s[1]; o.z = s[2];
    }
    g_v4[(size_t)b * NV + vtx] = o;
}

// ---------------------------------------------------------------------------
// K2: collect per-vertex opposite-edge pairs from faces (batch-independent).
// Face (f0,f1,f2): pair (f1,f2)->f0, (f2,f0)->f1, (f0,f1)->f2.
// Identity: summing full face normals around a closed ring telescopes to
// vn[v] = sum_i a_i x b_i over opposite-edge pairs.
// Thread 0 also resets the loss accumulator and ticket.
// ---------------------------------------------------------------------------
__global__ void k_ring(const int* __restrict__ faces, int F) {
    int f = blockIdx.x * blockDim.x + threadIdx.x;
    if (f == 0) { g_acc = 0.0; g_done = 0u; }
    if (f >= F) return;
    int a = faces[3 * f], b = faces[3 * f + 1], c = faces[3 * f + 2];
    int s;
    s = atomicAdd(&g_cnt[a], 1); g_ring[a * 6 + s] = make_int2(b, c);
    s = atomicAdd(&g_cnt[b], 1); g_ring[b * 6 + s] = make_int2(c, a);
    s = atomicAdd(&g_cnt[c], 1); g_ring[c * 6 + s] = make_int2(a, b);
}

// ---------------------------------------------------------------------------
// K3: fused loss. One thread per vertex, ALL 16 batches per thread.
// Chains pairs into cyclic ring order + rotates to minimal-index start
// (once per vertex — amortized over all batches). vn = sum_j n_j x n_{j+1};
// deg-5: slot 5 duplicates n_0 so the wrap cross term vanishes.
// Last block (ticket) writes the final scalar.
// ---------------------------------------------------------------------------
__global__ void __launch_bounds__(128)
k_loss(const float* __restrict__ target, float* __restrict__ out,
       unsigned int nblocks) {
    int vtx = blockIdx.x * blockDim.x + threadIdx.x;
    float local = 0.0f;
    if (vtx < NV) {
        int cnt = g_cnt[vtx];            // 5 or 6 == degree
        // vectorized ring-pair read: 6 int2 = 3 aligned int4
        const int4* rp = (const int4*)(g_ring + (size_t)vtx * 6);
        int4 r0 = rp[0], r1 = rp[1], r2 = rp[2];
        int2 pr[6] = { make_int2(r0.x, r0.y), make_int2(r0.z, r0.w),
                       make_int2(r1.x, r1.y), make_int2(r1.z, r1.w),
                       make_int2(r2.x, r2.y), make_int2(r2.z, r2.w) };
        if (cnt == 5) pr[5] = make_int2(-1, -1);
        // chain into cyclic order
        int ord[6];
        ord[0] = pr[0].x;
        int cur = pr[0].y;
        #pragma unroll
        for (int k = 1; k < 6; k++) {
            ord[k] = cur;
            int nxt = cur;
            #pragma unroll
            for (int i = 0; i < 6; i++)
                if (pr[i].x == cur) nxt = pr[i].y;
            cur = nxt;
        }
        // rotate to start at minimal neighbor index (cyclic-invariant)
        int best = 0;
        #pragma unroll
        for (int i = 1; i < 6; i++)
            if (i < cnt && ord[i] < ord[best]) best = i;
        int n[6];
        #pragma unroll
        for (int k = 0; k < 6; k++) {
            int idx = best + k;
            if (idx >= cnt) idx -= cnt;
            if (idx >= cnt) idx -= cnt;
            n[k] = ord[idx];
        }
        if (cnt == 5) n[5] = n[0];       // duplicated: wrap cross term = 0

        float invd = 1.0f / (float)cnt;
        const float inv3 = 1.0f / 3.0f;

        #pragma unroll 4
        for (int b = 0; b < BPT; b++) {
            const float4* vb = g_v4 + (size_t)b * NV;

            float4 p[6];
            #pragma unroll
            for (int i = 0; i < 6; i++) p[i] = __ldg(vb + n[i]);
            float4 pv = __ldg(vb + vtx);

            // ring-ordered cross sum: vn = sum_j p_j x p_{(j+1)%6}
            float nx = 0.f, ny = 0.f, nz = 0.f;
            #pragma unroll
            for (int j = 0; j < 6; j++) {
                const float4 a = p[j];
                const float4 c = p[(j + 1) % 6];
                nx += a.y * c.z - a.z * c.y;
                ny += a.z * c.x - a.x * c.z;
                nz += a.x * c.y - a.y * c.x;
            }
            // neighbor sum (subtract the duplicated n0 if deg==5)
            float sx = 0.f, sy = 0.f, sz = 0.f;
            #pragma unroll
            for (int j = 0; j < 6; j++) { sx += p[j].x; sy += p[j].y; sz += p[j].z; }
            if (cnt == 5) { sx -= p[0].x; sy -= p[0].y; sz -= p[0].z; }

            const float* t = target + (size_t)b * 9 * NV + vtx;
            // position loss (streamed target reads: evict-first)
            float dx = pv.x - __ldcs(t);
            float dy = pv.y - __ldcs(t + (size_t)NV);
            float dz = pv.z - __ldcs(t + 2 * (size_t)NV);
            float lpos = dx * dx + dy * dy + dz * dz;
            // normal cosine loss: ||n/||n|| || == 1, so cos = (u.t)/max(tn,eps')
            float nn  = sqrtf(nx * nx + ny * ny + nz * nz);
            float inv = 1.0f / fmaxf(nn, 1e-12f);
            float ux = nx * inv, uy = ny * inv, uz = nz * inv;
            float tx = __ldcs(t + 3 * (size_t)NV);
            float ty = __ldcs(t + 4 * (size_t)NV);
            float tz = __ldcs(t + 5 * (size_t)NV);
            float tn = sqrtf(tx * tx + ty * ty + tz * tz);
            float cosv = (ux * tx + uy * ty + uz * tz) / fmaxf(tn, 1e-8f);
            // Laplacian loss
            float dlx = (pv.x - sx * invd) - __ldcs(t + 6 * (size_t)NV);
            float dly = (pv.y - sy * invd) - __ldcs(t + 7 * (size_t)NV);
            float dlz = (pv.z - sz * invd) - __ldcs(t + 8 * (size_t)NV);
            float llap = dlx * dlx + dly * dly + dlz * dlz;

            local += (lpos + llap) * inv3 + (1.0f - cosv);
        }
    }

    // warp shuffle reduce, then cross-warp smem reduce, one atomic per block
    #pragma unroll
    for (int off = 16; off > 0; off >>= 1)
        local += __shfl_xor_sync(0xFFFFFFFFu, local, off);
    __shared__ float shw[4];
    int wid = threadIdx.x >> 5;
    if ((threadIdx.x & 31) == 0) shw[wid] = local;
    __syncthreads();
    if (threadIdx.x == 0) {
        float s = shw[0] + shw[1] + shw[2] + shw[3];
        atomicAdd(&g_acc, (double)s);
        __threadfence();
        unsigned int ticket = atomicAdd(&g_done, 1u);
        if (ticket == nblocks - 1u) {
            out[0] = (float)(g_acc / ((double)BATCH * (double)NV));
        }
    }
}

extern "C" void kernel_launch(void* const* d_in, const int* in_sizes, int n_in,
                              void* d_out, int out_size) {
    const float* inputs = (const float*)d_in[0];
    const float* target = (const float*)d_in[1];
    const int*   faces  = (const int*)  d_in[2];
    int F = in_sizes[2] / 3;

    // Fork-join overlap: topology chain (memset g_cnt -> k_ring) runs
    // concurrent with k_build_v. One-time setup on the eager call.
    static cudaStream_t s_side = nullptr;
    static cudaEvent_t  s_fork = nullptr, s_join = nullptr;
    static void* s_cnt_ptr = nullptr;
    if (s_side == nullptr) {
        cudaStreamCreateWithFlags(&s_side, cudaStreamNonBlocking);
        cudaEventCreateWithFlags(&s_fork, cudaEventDisableTiming);
        cudaEventCreateWithFlags(&s_join, cudaEventDisableTiming);
        cudaGetSymbolAddress(&s_cnt_ptr, g_cnt);
    }
    cudaStream_t main_s = 0;

    dim3 blk256(256);

    // fork
    cudaEventRecord(s_fork, main_s);
    cudaStreamWaitEvent(s_side, s_fork, 0);

    // side stream: zero counters (memset node) then build the ring pairs
    cudaMemsetAsync(s_cnt_ptr, 0, NV * sizeof(int), s_side);
    k_ring<<<(F + 255) / 256, blk256, 0, s_side>>>(faces, F);
    cudaEventRecord(s_join, s_side);

    // main stream: vertex build, concurrent with the side chain
    k_build_v<<<dim3((YX + 2 + 255) / 256, BATCH), blk256, 0, main_s>>>(inputs);

    // join, then fused loss (single pass over vertices, all batches)
    cudaStreamWaitEvent(main_s, s_join, 0);
    dim3 lgrid((NV + 127) / 128, 1);
    unsigned int nblocks = lgrid.x;
    k_loss<<<lgrid, 128, 0, main_s>>>(target, (float*)d_out, nblocks);
}

// round 13
// speedup vs baseline: 1.2795x; 1.2795x over previous
#include <cuda_runtime.h>

// Problem constants (SUBDIVISIONS=7, BATCH=16)
#define BATCH 16
#define YDIM  640
#define XDIM  256
#define BH    128            // YDIM/5
#define YX    (YDIM*XDIM)    // 163840
#define NV    (YX + 2)       // 163842 vertices
#define BPT   4              // batches per thread in the fused loss kernel
#define NFPT  4              // faces per thread in k_ring (atomic MLP)

// Scratch (static __device__ — no allocation allowed)
__device__ float4 g_v4[BATCH * NV];   // padded xyz_ per batch (~42 MB)
__device__ int    g_cnt[NV];          // per-vertex ring fill counters
__device__ int2   g_ring[NV * 6];     // per-vertex opposite-edge pairs (a,b)
__device__ double g_acc;              // fused loss accumulator
__device__ unsigned int g_done;       // ticket counter for fused finalization

// ---------------------------------------------------------------------------
// K1: build v = [grid verts ; top pole ; bottom pole] as float4 (w unused).
// inputs layout: (B, 3, Y, X) row-major
// ---------------------------------------------------------------------------
__global__ void k_build_v(const float* __restrict__ inp) {
    int vtx = blockIdx.x * blockDim.x + threadIdx.x;
    int b   = blockIdx.y;
    if (vtx > YX + 1) return;
    const float* base = inp + (size_t)b * 3 * YX;
    float4 o;
    o.w = 0.0f;
    if (vtx < YX) {
        o.x = base[vtx];
        o.y = base[YX + vtx];
        o.z = base[2 * YX + vtx];
    } else if (vtx == YX) {
        float s[3];
        #pragma unroll
        for (int c = 0; c < 3; c++) {
            s[c] = 0.0f;
            #pragma unroll
            for (int i = 0; i < 5; i++) s[c] += base[c * YX + (i * BH) * XDIM];
            s[c] *= 0.2f;
        }
        o.x = s[0]; o.y = s[1]; o.z = s[2];
    } else {
        float s[3];
        #pragma unroll
        for (int c = 0; c < 3; c++) {
            s[c] = 0.0f;
            #pragma unroll
            for (int i = 1; i <= 5; i++)
                s[c] += base[c * YX + (i * BH - 1) * XDIM + (XDIM - 1)];
            s[c] *= 0.2f;
        }
        o.x = s[0]; o.y = s[1]; o.z = s[2];
    }
    g_v4[(size_t)b * NV + vtx] = o;
}

// ---------------------------------------------------------------------------
// K2: collect per-vertex opposite-edge pairs from faces (batch-independent).
// Face (f0,f1,f2): pair (f1,f2)->f0, (f2,f0)->f1, (f0,f1)->f2.
// NFPT faces per thread (stride-partitioned so face reads stay coalesced):
// 3*NFPT independent atomic chains per thread hide the ~320-cycle ATOMG
// return latency that made the 1-face version issue-starved.
// Thread 0 also resets the loss accumulator and ticket.
// ---------------------------------------------------------------------------
__global__ void k_ring(const int* __restrict__ faces, int F, int Q) {
    int i = blockIdx.x * blockDim.x + threadIdx.x;
    if (i == 0) { g_acc = 0.0; g_done = 0u; }
    #pragma unroll
    for (int k = 0; k < NFPT; k++) {
        int f = i + k * Q;
        if (f < F) {
            int a = faces[3 * f], b = faces[3 * f + 1], c = faces[3 * f + 2];
            int s;
            s = atomicAdd(&g_cnt[a], 1); g_ring[a * 6 + s] = make_int2(b, c);
            s = atomicAdd(&g_cnt[b], 1); g_ring[b * 6 + s] = make_int2(c, a);
            s = atomicAdd(&g_cnt[c], 1); g_ring[c * 6 + s] = make_int2(a, b);
        }
    }
}

// ---------------------------------------------------------------------------
// K3: fused loss (identical to the 77.9us best). One thread per vertex,
// BPT batches per thread. Chains pairs into cyclic ring order + rotates to
// minimal-index start in registers; vn = sum_j n_j x n_{j+1 mod 6}; deg-5:
// slot 5 duplicates n_0 so the wrap cross term vanishes.
// Last block (ticket) writes the final scalar.
// ---------------------------------------------------------------------------
__global__ void __launch_bounds__(128)
k_loss(const float* __restrict__ target, float* __restrict__ out,
       unsigned int nblocks) {
    int vtx = blockIdx.x * blockDim.x + threadIdx.x;
    float local = 0.0f;
    if (vtx < NV) {
        int cnt = g_cnt[vtx];            // 5 or 6 == degree
        int2 pr[6];
        #pragma unroll
        for (int i = 0; i < 6; i++)
            pr[i] = (i < cnt) ? g_ring[vtx * 6 + i] : make_int2(-1, -1);
        // chain into cyclic order
        int ord[6];
        ord[0] = pr[0].x;
        int cur = pr[0].y;
        #pragma unroll
        for (int k = 1; k < 6; k++) {
            ord[k] = cur;
            int nxt = cur;
            #pragma unroll
            for (int i = 0; i < 6; i++)
                if (pr[i].x == cur) nxt = pr[i].y;
            cur = nxt;
        }
        // rotate to start at minimal neighbor index (cyclic-invariant,
        // improves warp gather coalescing)
        int best = 0;
        #pragma unroll
        for (int i = 1; i < 6; i++)
            if (i < cnt && ord[i] < ord[best]) best = i;
        int n[6];
        #pragma unroll
        for (int k = 0; k < 6; k++) {
            int idx = best + k;
            if (idx >= cnt) idx -= cnt;
            if (idx >= cnt) idx -= cnt;
            n[k] = ord[idx];
        }
        if (cnt == 5) n[5] = n[0];       // duplicated: wrap cross term = 0

        float invd = 1.0f / (float)cnt;
        const float inv3 = 1.0f / 3.0f;

        #pragma unroll
        for (int bb = 0; bb < BPT; bb++) {
            int b = blockIdx.y * BPT + bb;
            const float4* vb = g_v4 + (size_t)b * NV;

            float4 p[6];
            #pragma unroll
            for (int i = 0; i < 6; i++) p[i] = __ldg(vb + n[i]);
            float4 pv = __ldg(vb + vtx);

            // ring-ordered cross sum: vn = sum_j p_j x p_{(j+1)%6}
            float nx = 0.f, ny = 0.f, nz = 0.f;
            #pragma unroll
            for (int j = 0; j < 6; j++) {
                const float4 a = p[j];
                const float4 c = p[(j + 1) % 6];
                nx += a.y * c.z - a.z * c.y;
                ny += a.z * c.x - a.x * c.z;
                nz += a.x * c.y - a.y * c.x;
            }
            // neighbor sum (subtract the duplicated n0 if deg==5)
            float sx = 0.f, sy = 0.f, sz = 0.f;
            #pragma unroll
            for (int j = 0; j < 6; j++) { sx += p[j].x; sy += p[j].y; sz += p[j].z; }
            if (cnt == 5) { sx -= p[0].x; sy -= p[0].y; sz -= p[0].z; }

            const float* t = target + (size_t)b * 9 * NV + vtx;
            // position loss (streamed target reads: evict-first)
            float dx = pv.x - __ldcs(t);
            float dy = pv.y - __ldcs(t + (size_t)NV);
            float dz = pv.z - __ldcs(t + 2 * (size_t)NV);
            float lpos = dx * dx + dy * dy + dz * dz;
            // normal cosine loss
            float nn  = sqrtf(nx * nx + ny * ny + nz * nz);
            float inv = 1.0f / fmaxf(nn, 1e-12f);
            float ux = nx * inv, uy = ny * inv, uz = nz * inv;
            float un = sqrtf(ux * ux + uy * uy + uz * uz);
            float tx = __ldcs(t + 3 * (size_t)NV);
            float ty = __ldcs(t + 4 * (size_t)NV);
            float tz = __ldcs(t + 5 * (size_t)NV);
            float tn = sqrtf(tx * tx + ty * ty + tz * tz);
            float cosv = (ux * tx + uy * ty + uz * tz) / fmaxf(un * tn, 1e-8f);
            // Laplacian loss
            float dlx = (pv.x - sx * invd) - __ldcs(t + 6 * (size_t)NV);
            float dly = (pv.y - sy * invd) - __ldcs(t + 7 * (size_t)NV);
            float dlz = (pv.z - sz * invd) - __ldcs(t + 8 * (size_t)NV);
            float llap = dlx * dlx + dly * dly + dlz * dlz;

            local += (lpos + llap) * inv3 + (1.0f - cosv);
        }
    }

    // warp shuffle reduce, then cross-warp smem reduce, one atomic per block
    #pragma unroll
    for (int off = 16; off > 0; off >>= 1)
        local += __shfl_xor_sync(0xFFFFFFFFu, local, off);
    __shared__ float shw[4];
    int wid = threadIdx.x >> 5;
    if ((threadIdx.x & 31) == 0) shw[wid] = local;
    __syncthreads();
    if (threadIdx.x == 0) {
        float s = shw[0] + shw[1] + shw[2] + shw[3];
        atomicAdd(&g_acc, (double)s);
        __threadfence();
        unsigned int ticket = atomicAdd(&g_done, 1u);
        if (ticket == nblocks - 1u) {
            out[0] = (float)(g_acc / ((double)BATCH * (double)NV));
        }
    }
}

extern "C" void kernel_launch(void* const* d_in, const int* in_sizes, int n_in,
                              void* d_out, int out_size) {
    const float* inputs = (const float*)d_in[0];
    const float* target = (const float*)d_in[1];
    const int*   faces  = (const int*)  d_in[2];
    int F = in_sizes[2] / 3;

    // Fork-join overlap: topology chain (memset g_cnt -> k_ring) runs
    // concurrent with k_build_v. One-time setup on the eager call.
    static cudaStream_t s_side = nullptr;
    static cudaEvent_t  s_fork = nullptr, s_join = nullptr;
    static void* s_cnt_ptr = nullptr;
    if (s_side == nullptr) {
        cudaStreamCreateWithFlags(&s_side, cudaStreamNonBlocking);
        cudaEventCreateWithFlags(&s_fork, cudaEventDisableTiming);
        cudaEventCreateWithFlags(&s_join, cudaEventDisableTiming);
        cudaGetSymbolAddress(&s_cnt_ptr, g_cnt);
    }
    cudaStream_t main_s = 0;

    dim3 blk256(256);

    // fork
    cudaEventRecord(s_fork, main_s);
    cudaStreamWaitEvent(s_side, s_fork, 0);

    // side stream: zero counters (memset node) then build the ring pairs
    cudaMemsetAsync(s_cnt_ptr, 0, NV * sizeof(int), s_side);
    int Q = (F + NFPT - 1) / NFPT;   // stride between a thread's faces
    k_ring<<<(Q + 255) / 256, blk256, 0, s_side>>>(faces, F, Q);
    cudaEventRecord(s_join, s_side);

    // main stream: vertex build, concurrent with the side chain
    k_build_v<<<dim3((YX + 2 + 255) / 256, BATCH), blk256, 0, main_s>>>(inputs);

    // join, then fused loss (chains + rotates rings inline)
    cudaStreamWaitEvent(main_s, s_join, 0);
    dim3 lgrid((NV + 127) / 128, BATCH / BPT);
    unsigned int nblocks = lgrid.x * lgrid.y;
    k_loss<<<lgrid, 128, 0, main_s>>>(target, (float*)d_out, nblocks);
}

// round 14
// speedup vs baseline: 1.3515x; 1.0563x over previous
#include <cuda_runtime.h>

// Problem constants (SUBDIVISIONS=7, BATCH=16)
#define BATCH 16
#define YDIM  640
#define XDIM  256
#define BH    128            // YDIM/5
#define YX    (YDIM*XDIM)    // 163840
#define NV    (YX + 2)       // 163842 vertices
#define BPT   4              // batches per thread in the fused loss kernel

// CSR over the sorted unique directed edge list (np.unique -> lexicographic):
// deg(v) = 5 for the 12 original icosahedron vertices (indices 0..11),
// 6 otherwise; offset(v) = prefix sum, closed form.
__device__ __forceinline__ int csr_off(int v) { return v < 12 ? 5 * v : 6 * v - 12; }
__device__ __forceinline__ int csr_deg(int v) { return v < 12 ? 5 : 6; }

// Scratch (static __device__ — no allocation allowed)
__device__ float4 g_v4[BATCH * NV];   // padded xyz_ per batch (~42 MB)
__device__ int    g_succ[NV * 6];     // ring-successor per directed edge slot
__device__ double g_acc;              // fused loss accumulator
__device__ unsigned int g_done;       // ticket counter for fused finalization

// ---------------------------------------------------------------------------
// K1: build v = [grid verts ; top pole ; bottom pole] as float4 (w unused).
// inputs layout: (B, 3, Y, X) row-major
// ---------------------------------------------------------------------------
__global__ void k_build_v(const float* __restrict__ inp) {
    int vtx = blockIdx.x * blockDim.x + threadIdx.x;
    int b   = blockIdx.y;
    if (vtx > YX + 1) return;
    const float* base = inp + (size_t)b * 3 * YX;
    float4 o;
    o.w = 0.0f;
    if (vtx < YX) {
        o.x = base[vtx];
        o.y = base[YX + vtx];
        o.z = base[2 * YX + vtx];
    } else if (vtx == YX) {
        float s[3];
        #pragma unroll
        for (int c = 0; c < 3; c++) {
            s[c] = 0.0f;
            #pragma unroll
            for (int i = 0; i < 5; i++) s[c] += base[c * YX + (i * BH) * XDIM];
            s[c] *= 0.2f;
        }
        o.x = s[0]; o.y = s[1]; o.z = s[2];
    } else {
        float s[3];
        #pragma unroll
        for (int c = 0; c < 3; c++) {
            s[c] = 0.0f;
            #pragma unroll
            for (int i = 1; i <= 5; i++)
                s[c] += base[c * YX + (i * BH - 1) * XDIM + (XDIM - 1)];
            s[c] *= 0.2f;
        }
        o.x = s[0]; o.y = s[1]; o.z = s[2];
    }
    g_v4[(size_t)b * NV + vtx] = o;
}

// ---------------------------------------------------------------------------
// K2: build the ring-successor map with NO atomics.
// Face (v,a,b) (oriented) defines succ(v->a) = b for each cyclic corner.
// The slot for directed edge v->a is its position in v's sorted CSR neighbor
// segment of edge_dst — unique per directed edge (each directed edge lies in
// exactly one oriented face), so every slot is written exactly once and no
// counter/memset is needed. Thread 0 resets the loss accumulator + ticket.
// ---------------------------------------------------------------------------
__device__ __forceinline__ void store_succ(const int* __restrict__ edst,
                                           int v, int a, int b) {
    int off = csr_off(v);
    int cnt = csr_deg(v);
    int pos = 0;
    #pragma unroll
    for (int i = 0; i < 6; i++)
        if (i < cnt && edst[off + i] == a) pos = i;
    g_succ[off + pos] = b;
}

__global__ void k_ring(const int* __restrict__ faces,
                       const int* __restrict__ edst, int F) {
    int f = blockIdx.x * blockDim.x + threadIdx.x;
    if (f == 0) { g_acc = 0.0; g_done = 0u; }
    if (f >= F) return;
    int a = faces[3 * f], b = faces[3 * f + 1], c = faces[3 * f + 2];
    store_succ(edst, a, b, c);
    store_succ(edst, b, c, a);
    store_succ(edst, c, a, b);
}

// ---------------------------------------------------------------------------
// K3: fused loss. One thread per vertex, BPT batches per thread.
// Neighbor list d[] comes from the sorted CSR edge_dst segment (coalesced:
// consecutive vertices own consecutive 6-int segments); ring order walks
// g_succ. d[0] is the minimal neighbor, so the coalescing rotation is free.
// deg-5: slot 5 duplicates n[0] so the wrap cross term vanishes.
// Last block (ticket) writes the final scalar.
// ---------------------------------------------------------------------------
__global__ void __launch_bounds__(128)
k_loss(const int* __restrict__ edst, const float* __restrict__ target,
       float* __restrict__ out, unsigned int nblocks) {
    int vtx = blockIdx.x * blockDim.x + threadIdx.x;
    float local = 0.0f;
    if (vtx < NV) {
        int off = csr_off(vtx);
        int cnt = csr_deg(vtx);
        int d[6], s[6];
        #pragma unroll
        for (int i = 0; i < 6; i++) {
            // off+5 <= E-1 even for the last vertex (off(NV-1)+6 == E)
            d[i] = edst[off + i];
            s[i] = g_succ[off + i];
        }
        // walk the ring: start at the minimal neighbor d[0]
        int n[6];
        n[0] = d[0];
        int nxt = s[0];
        #pragma unroll
        for (int k = 1; k < 6; k++) {
            n[k] = nxt;
            int nn_ = nxt;
            #pragma unroll
            for (int i = 0; i < 6; i++)
                if (i < cnt && d[i] == nxt) nn_ = s[i];
            nxt = nn_;
        }
        if (cnt == 5) n[5] = n[0];       // duplicated: wrap cross term = 0

        float invd = 1.0f / (float)cnt;
        const float inv3 = 1.0f / 3.0f;

        #pragma unroll
        for (int bb = 0; bb < BPT; bb++) {
            int b = blockIdx.y * BPT + bb;
            const float4* vb = g_v4 + (size_t)b * NV;

            float4 p[6];
            #pragma unroll
            for (int i = 0; i < 6; i++) p[i] = __ldg(vb + n[i]);
            float4 pv = __ldg(vb + vtx);

            // ring-ordered cross sum: vn = sum_j p_j x p_{(j+1)%6}
            float nx = 0.f, ny = 0.f, nz = 0.f;
            #pragma unroll
            for (int j = 0; j < 6; j++) {
                const float4 a = p[j];
                const float4 c = p[(j + 1) % 6];
                nx += a.y * c.z - a.z * c.y;
                ny += a.z * c.x - a.x * c.z;
                nz += a.x * c.y - a.y * c.x;
            }
            // neighbor sum (subtract the duplicated n0 if deg==5)
            float sx = 0.f, sy = 0.f, sz = 0.f;
            #pragma unroll
            for (int j = 0; j < 6; j++) { sx += p[j].x; sy += p[j].y; sz += p[j].z; }
            if (cnt == 5) { sx -= p[0].x; sy -= p[0].y; sz -= p[0].z; }

            const float* t = target + (size_t)b * 9 * NV + vtx;
            // position loss (streamed target reads: evict-first)
            float dx = pv.x - __ldcs(t);
            float dy = pv.y - __ldcs(t + (size_t)NV);
            float dz = pv.z - __ldcs(t + 2 * (size_t)NV);
            float lpos = dx * dx + dy * dy + dz * dz;
            // normal cosine loss
            float nn  = sqrtf(nx * nx + ny * ny + nz * nz);
            float inv = 1.0f / fmaxf(nn, 1e-12f);
            float ux = nx * inv, uy = ny * inv, uz = nz * inv;
            float un = sqrtf(ux * ux + uy * uy + uz * uz);
            float tx = __ldcs(t + 3 * (size_t)NV);
            float ty = __ldcs(t + 4 * (size_t)NV);
            float tz = __ldcs(t + 5 * (size_t)NV);
            float tn = sqrtf(tx * tx + ty * ty + tz * tz);
            float cosv = (ux * tx + uy * ty + uz * tz) / fmaxf(un * tn, 1e-8f);
            // Laplacian loss
            float dlx = (pv.x - sx * invd) - __ldcs(t + 6 * (size_t)NV);
            float dly = (pv.y - sy * invd) - __ldcs(t + 7 * (size_t)NV);
            float dlz = (pv.z - sz * invd) - __ldcs(t + 8 * (size_t)NV);
            float llap = dlx * dlx + dly * dly + dlz * dlz;

            local += (lpos + llap) * inv3 + (1.0f - cosv);
        }
    }

    // warp shuffle reduce, then cross-warp smem reduce, one atomic per block
    #pragma unroll
    for (int off2 = 16; off2 > 0; off2 >>= 1)
        local += __shfl_xor_sync(0xFFFFFFFFu, local, off2);
    __shared__ float shw[4];
    int wid = threadIdx.x >> 5;
    if ((threadIdx.x & 31) == 0) shw[wid] = local;
    __syncthreads();
    if (threadIdx.x == 0) {
        float s = shw[0] + shw[1] + shw[2] + shw[3];
        atomicAdd(&g_acc, (double)s);
        __threadfence();
        unsigned int ticket = atomicAdd(&g_done, 1u);
        if (ticket == nblocks - 1u) {
            out[0] = (float)(g_acc / ((double)BATCH * (double)NV));
        }
    }
}

extern "C" void kernel_launch(void* const* d_in, const int* in_sizes, int n_in,
                              void* d_out, int out_size) {
    const float* inputs = (const float*)d_in[0];
    const float* target = (const float*)d_in[1];
    const int*   faces  = (const int*)  d_in[2];
    const int*   edst   = (const int*)  d_in[4];
    int F = in_sizes[2] / 3;

    // Fork-join overlap: the succ-map build (atomic-free) runs concurrent
    // with k_build_v. One-time stream/event setup on the eager call.
    static cudaStream_t s_side = nullptr;
    static cudaEvent_t  s_fork = nullptr, s_join = nullptr;
    if (s_side == nullptr) {
        cudaStreamCreateWithFlags(&s_side, cudaStreamNonBlocking);
        cudaEventCreateWithFlags(&s_fork, cudaEventDisableTiming);
        cudaEventCreateWithFlags(&s_join, cudaEventDisableTiming);
    }
    cudaStream_t main_s = 0;

    dim3 blk256(256);

    // fork
    cudaEventRecord(s_fork, main_s);
    cudaStreamWaitEvent(s_side, s_fork, 0);

    // side stream: build ring-successor map (no atomics, no memset)
    k_ring<<<(F + 255) / 256, blk256, 0, s_side>>>(faces, edst, F);
    cudaEventRecord(s_join, s_side);

    // main stream: vertex build, concurrent with the side chain
    k_build_v<<<dim3((YX + 2 + 255) / 256, BATCH), blk256, 0, main_s>>>(inputs);

    // join, then fused loss
    cudaStreamWaitEvent(main_s, s_join, 0);
    dim3 lgrid((NV + 127) / 128, BATCH / BPT);
    unsigned int nblocks = lgrid.x * lgrid.y;
    k_loss<<<lgrid, 128, 0, main_s>>>(edst, target, (float*)d_out, nblocks);
}

// round 15
// speedup vs baseline: 1.3873x; 1.0265x over previous
#include <cuda_runtime.h>

// Problem constants (SUBDIVISIONS=7, BATCH=16)
#define BATCH 16
#define YDIM  640
#define XDIM  256
#define BH    128            // YDIM/5
#define YX    (YDIM*XDIM)    // 163840
#define NV    (YX + 2)       // 163842 vertices
#define BPT   4              // batches per thread in the fused loss kernel

// CSR over the sorted unique directed edge list (np.unique -> lexicographic):
// deg(v) = 5 for the 12 original icosahedron vertices (indices 0..11),
// 6 otherwise; offset(v) = prefix sum, closed form.
__device__ __forceinline__ int csr_off(int v) { return v < 12 ? 5 * v : 6 * v - 12; }
__device__ __forceinline__ int csr_deg(int v) { return v < 12 ? 5 : 6; }

// Scratch (static __device__ — no allocation allowed)
__device__ float4 g_v4[BATCH * NV];   // padded xyz_ per batch (~42 MB)
__device__ int    g_succ[NV * 6];     // ring-successor per directed edge slot
__device__ double g_acc;              // fused loss accumulator
__device__ unsigned int g_done;       // ticket counter for fused finalization

// ---------------------------------------------------------------------------
// K1: build v = [grid verts ; top pole ; bottom pole] as float4 (w unused).
// inputs layout: (B, 3, Y, X) row-major
// ---------------------------------------------------------------------------
__global__ void k_build_v(const float* __restrict__ inp) {
    int vtx = blockIdx.x * blockDim.x + threadIdx.x;
    int b   = blockIdx.y;
    if (vtx > YX + 1) return;
    const float* base = inp + (size_t)b * 3 * YX;
    float4 o;
    o.w = 0.0f;
    if (vtx < YX) {
        o.x = base[vtx];
        o.y = base[YX + vtx];
        o.z = base[2 * YX + vtx];
    } else if (vtx == YX) {
        float s[3];
        #pragma unroll
        for (int c = 0; c < 3; c++) {
            s[c] = 0.0f;
            #pragma unroll
            for (int i = 0; i < 5; i++) s[c] += base[c * YX + (i * BH) * XDIM];
            s[c] *= 0.2f;
        }
        o.x = s[0]; o.y = s[1]; o.z = s[2];
    } else {
        float s[3];
        #pragma unroll
        for (int c = 0; c < 3; c++) {
            s[c] = 0.0f;
            #pragma unroll
            for (int i = 1; i <= 5; i++)
                s[c] += base[c * YX + (i * BH - 1) * XDIM + (XDIM - 1)];
            s[c] *= 0.2f;
        }
        o.x = s[0]; o.y = s[1]; o.z = s[2];
    }
    g_v4[(size_t)b * NV + vtx] = o;
}

// ---------------------------------------------------------------------------
// K2: build the ring-successor map with NO atomics.
// Face (v,a,b) (oriented) defines succ(v->a) = b. The slot for directed edge
// v->a is a's position in v's sorted CSR segment of edge_dst — unique per
// directed edge, so each slot is written exactly once (no counters/memset).
// For v>=12, csr_off(v)=6v-12 is even -> the segment is 8B-aligned: scan it
// with three LDG.64 instead of six LDG.32, halving the scattered-gather
// wavefront count that dominates this kernel. v<12 (60 corners total) takes
// the scalar path. Thread 0 resets the loss accumulator + ticket.
// ---------------------------------------------------------------------------
__device__ __forceinline__ void store_succ(const int* __restrict__ edst,
                                           int v, int a, int b) {
    if (v >= 12) {
        int off = 6 * v - 12;
        const int2* p = (const int2*)(edst + off);
        int2 q0 = __ldg(p), q1 = __ldg(p + 1), q2 = __ldg(p + 2);
        int pos = 0;
        if (q0.y == a) pos = 1;
        if (q1.x == a) pos = 2;
        if (q1.y == a) pos = 3;
        if (q2.x == a) pos = 4;
        if (q2.y == a) pos = 5;
        g_succ[off + pos] = b;
    } else {
        int off = 5 * v;
        int pos = 0;
        #pragma unroll
        for (int i = 0; i < 5; i++)
            if (__ldg(edst + off + i) == a) pos = i;
        g_succ[off + pos] = b;
    }
}

__global__ void k_ring(const int* __restrict__ faces,
                       const int* __restrict__ edst, int F) {
    int f = blockIdx.x * blockDim.x + threadIdx.x;
    if (f == 0) { g_acc = 0.0; g_done = 0u; }
    if (f >= F) return;
    int a = faces[3 * f], b = faces[3 * f + 1], c = faces[3 * f + 2];
    store_succ(edst, a, b, c);
    store_succ(edst, b, c, a);
    store_succ(edst, c, a, b);
}

// ---------------------------------------------------------------------------
// K3: fused loss (identical to the 75.6us best). One thread per vertex,
// BPT batches per thread. Neighbor list d[] from the sorted CSR edge_dst
// segment (coalesced); ring order walks g_succ; d[0] is the minimal
// neighbor so the coalescing rotation is free. deg-5: slot 5 duplicates
// n[0] so the wrap cross term vanishes. Last block writes the scalar.
// ---------------------------------------------------------------------------
__global__ void __launch_bounds__(128)
k_loss(const int* __restrict__ edst, const float* __restrict__ target,
       float* __restrict__ out, unsigned int nblocks) {
    int vtx = blockIdx.x * blockDim.x + threadIdx.x;
    float local = 0.0f;
    if (vtx < NV) {
        int off = csr_off(vtx);
        int cnt = csr_deg(vtx);
        int d[6], s[6];
        #pragma unroll
        for (int i = 0; i < 6; i++) {
            // off+5 <= E-1 even for the last vertex (off(NV-1)+6 == E)
            d[i] = edst[off + i];
            s[i] = g_succ[off + i];
        }
        // walk the ring: start at the minimal neighbor d[0]
        int n[6];
        n[0] = d[0];
        int nxt = s[0];
        #pragma unroll
        for (int k = 1; k < 6; k++) {
            n[k] = nxt;
            int nn_ = nxt;
            #pragma unroll
            for (int i = 0; i < 6; i++)
                if (i < cnt && d[i] == nxt) nn_ = s[i];
            nxt = nn_;
        }
        if (cnt == 5) n[5] = n[0];       // duplicated: wrap cross term = 0

        float invd = 1.0f / (float)cnt;
        const float inv3 = 1.0f / 3.0f;

        #pragma unroll
        for (int bb = 0; bb < BPT; bb++) {
            int b = blockIdx.y * BPT + bb;
            const float4* vb = g_v4 + (size_t)b * NV;

            float4 p[6];
            #pragma unroll
            for (int i = 0; i < 6; i++) p[i] = __ldg(vb + n[i]);
            float4 pv = __ldg(vb + vtx);

            // ring-ordered cross sum: vn = sum_j p_j x p_{(j+1)%6}
            float nx = 0.f, ny = 0.f, nz = 0.f;
            #pragma unroll
            for (int j = 0; j < 6; j++) {
                const float4 a = p[j];
                const float4 c = p[(j + 1) % 6];
                nx += a.y * c.z - a.z * c.y;
                ny += a.z * c.x - a.x * c.z;
                nz += a.x * c.y - a.y * c.x;
            }
            // neighbor sum (subtract the duplicated n0 if deg==5)
            float sx = 0.f, sy = 0.f, sz = 0.f;
            #pragma unroll
            for (int j = 0; j < 6; j++) { sx += p[j].x; sy += p[j].y; sz += p[j].z; }
            if (cnt == 5) { sx -= p[0].x; sy -= p[0].y; sz -= p[0].z; }

            const float* t = target + (size_t)b * 9 * NV + vtx;
            // position loss (streamed target reads: evict-first)
            float dx = pv.x - __ldcs(t);
            float dy = pv.y - __ldcs(t + (size_t)NV);
            float dz = pv.z - __ldcs(t + 2 * (size_t)NV);
            float lpos = dx * dx + dy * dy + dz * dz;
            // normal cosine loss
            float nn  = sqrtf(nx * nx + ny * ny + nz * nz);
            float inv = 1.0f / fmaxf(nn, 1e-12f);
            float ux = nx * inv, uy = ny * inv, uz = nz * inv;
            float un = sqrtf(ux * ux + uy * uy + uz * uz);
            float tx = __ldcs(t + 3 * (size_t)NV);
            float ty = __ldcs(t + 4 * (size_t)NV);
            float tz = __ldcs(t + 5 * (size_t)NV);
            float tn = sqrtf(tx * tx + ty * ty + tz * tz);
            float cosv = (ux * tx + uy * ty + uz * tz) / fmaxf(un * tn, 1e-8f);
            // Laplacian loss
            float dlx = (pv.x - sx * invd) - __ldcs(t + 6 * (size_t)NV);
            float dly = (pv.y - sy * invd) - __ldcs(t + 7 * (size_t)NV);
            float dlz = (pv.z - sz * invd) - __ldcs(t + 8 * (size_t)NV);
            float llap = dlx * dlx + dly * dly + dlz * dlz;

            local += (lpos + llap) * inv3 + (1.0f - cosv);
        }
    }

    // warp shuffle reduce, then cross-warp smem reduce, one atomic per block
    #pragma unroll
    for (int off2 = 16; off2 > 0; off2 >>= 1)
        local += __shfl_xor_sync(0xFFFFFFFFu, local, off2);
    __shared__ float shw[4];
    int wid = threadIdx.x >> 5;
    if ((threadIdx.x & 31) == 0) shw[wid] = local;
    __syncthreads();
    if (threadIdx.x == 0) {
        float s = shw[0] + shw[1] + shw[2] + shw[3];
        atomicAdd(&g_acc, (double)s);
        __threadfence();
        unsigned int ticket = atomicAdd(&g_done, 1u);
        if (ticket == nblocks - 1u) {
            out[0] = (float)(g_acc / ((double)BATCH * (double)NV));
        }
    }
}

extern "C" void kernel_launch(void* const* d_in, const int* in_sizes, int n_in,
                              void* d_out, int out_size) {
    const float* inputs = (const float*)d_in[0];
    const float* target = (const float*)d_in[1];
    const int*   faces  = (const int*)  d_in[2];
    const int*   edst   = (const int*)  d_in[4];
    int F = in_sizes[2] / 3;

    // Fork-join overlap: the succ-map build (atomic-free) runs concurrent
    // with k_build_v. One-time stream/event setup on the eager call.
    static cudaStream_t s_side = nullptr;
    static cudaEvent_t  s_fork = nullptr, s_join = nullptr;
    if (s_side == nullptr) {
        cudaStreamCreateWithFlags(&s_side, cudaStreamNonBlocking);
        cudaEventCreateWithFlags(&s_fork, cudaEventDisableTiming);
        cudaEventCreateWithFlags(&s_join, cudaEventDisableTiming);
    }
    cudaStream_t main_s = 0;

    dim3 blk256(256);

    // fork
    cudaEventRecord(s_fork, main_s);
    cudaStreamWaitEvent(s_side, s_fork, 0);

    // side stream: build ring-successor map (no atomics, vectorized scans)
    k_ring<<<(F + 255) / 256, blk256, 0, s_side>>>(faces, edst, F);
    cudaEventRecord(s_join, s_side);

    // main stream: vertex build, concurrent with the side chain
    k_build_v<<<dim3((YX + 2 + 255) / 256, BATCH), blk256, 0, main_s>>>(inputs);

    // join, then fused loss
    cudaStreamWaitEvent(main_s, s_join, 0);
    dim3 lgrid((NV + 127) / 128, BATCH / BPT);
    unsigned int nblocks = lgrid.x * lgrid.y;
    k_loss<<<lgrid, 128, 0, main_s>>>(edst, target, (float*)d_out, nblocks);
}

// round 16
// speedup vs baseline: 1.4100x; 1.0163x over previous
#include <cuda_runtime.h>

// Problem constants (SUBDIVISIONS=7, BATCH=16)
#define BATCH 16
#define YDIM  640
#define XDIM  256
#define BH    128            // YDIM/5
#define YX    (YDIM*XDIM)    // 163840
#define NV    (YX + 2)       // 163842 vertices
#define BPT   4              // batches per thread in the fused loss kernel

// CSR over the sorted unique directed edge list (np.unique -> lexicographic):
// deg(v) = 5 for the 12 original icosahedron vertices (indices 0..11),
// 6 otherwise; offset(v) = prefix sum, closed form.
__device__ __forceinline__ int csr_off(int v) { return v < 12 ? 5 * v : 6 * v - 12; }
__device__ __forceinline__ int csr_deg(int v) { return v < 12 ? 5 : 6; }

// Scratch (static __device__ — no allocation allowed)
__device__ float4 g_v4[BATCH * NV];   // padded xyz_ per batch (~42 MB)
__device__ int    g_succ[NV * 6];     // ring-successor per directed edge slot
__device__ double g_acc;              // fused loss accumulator
__device__ unsigned int g_done;       // ticket counter for fused finalization

// ---------------------------------------------------------------------------
// K1: build v = [grid verts ; top pole ; bottom pole] as float4 (w unused).
// inputs layout: (B, 3, Y, X) row-major
// ---------------------------------------------------------------------------
__global__ void k_build_v(const float* __restrict__ inp) {
    int vtx = blockIdx.x * blockDim.x + threadIdx.x;
    int b   = blockIdx.y;
    if (vtx > YX + 1) return;
    const float* base = inp + (size_t)b * 3 * YX;
    float4 o;
    o.w = 0.0f;
    if (vtx < YX) {
        o.x = base[vtx];
        o.y = base[YX + vtx];
        o.z = base[2 * YX + vtx];
    } else if (vtx == YX) {
        float s[3];
        #pragma unroll
        for (int c = 0; c < 3; c++) {
            s[c] = 0.0f;
            #pragma unroll
            for (int i = 0; i < 5; i++) s[c] += base[c * YX + (i * BH) * XDIM];
            s[c] *= 0.2f;
        }
        o.x = s[0]; o.y = s[1]; o.z = s[2];
    } else {
        float s[3];
        #pragma unroll
        for (int c = 0; c < 3; c++) {
            s[c] = 0.0f;
            #pragma unroll
            for (int i = 1; i <= 5; i++)
                s[c] += base[c * YX + (i * BH - 1) * XDIM + (XDIM - 1)];
            s[c] *= 0.2f;
        }
        o.x = s[0]; o.y = s[1]; o.z = s[2];
    }
    g_v4[(size_t)b * NV + vtx] = o;
}

// ---------------------------------------------------------------------------
// K2: build the ring-successor map with NO atomics.
// Face (v,a,b) (oriented) defines succ(v->a) = b. The slot for directed edge
// v->a is a's position in v's sorted CSR segment of edge_dst — unique per
// directed edge, so each slot is written exactly once (no counters/memset).
// The 6-int segment [off, off+6), off = 6v-12, always lies inside the two
// aligned 16B words at base = off & ~3 (off-base in {0,2}; worst-case read
// base+7 == E-1, in range). Two LDG.128 + uniform selects replace the three
// scattered LDG.64 — ~33% fewer gather wavefronts. v<12 (60 corners) takes
// a scalar path. Thread 0 resets the loss accumulator + ticket.
// ---------------------------------------------------------------------------
__device__ __forceinline__ void store_succ(const int* __restrict__ edst,
                                           int v, int a, int b) {
    if (v >= 12) {
        int off  = 6 * v - 12;
        int base = off & ~3;
        const int4* P = (const int4*)(edst + base);
        int4 A = __ldg(P), B = __ldg(P + 1);
        int e0, e1, e2, e3, e4, e5;
        if (off & 2) { e0 = A.z; e1 = A.w; e2 = B.x; e3 = B.y; e4 = B.z; e5 = B.w; }
        else         { e0 = A.x; e1 = A.y; e2 = A.z; e3 = A.w; e4 = B.x; e5 = B.y; }
        int pos = 0;
        if (e1 == a) pos = 1;
        if (e2 == a) pos = 2;
        if (e3 == a) pos = 3;
        if (e4 == a) pos = 4;
        if (e5 == a) pos = 5;
        g_succ[off + pos] = b;
    } else {
        int off = 5 * v;
        int pos = 0;
        #pragma unroll
        for (int i = 0; i < 5; i++)
            if (__ldg(edst + off + i) == a) pos = i;
        g_succ[off + pos] = b;
    }
}

__global__ void k_ring(const int* __restrict__ faces,
                       const int* __restrict__ edst, int F) {
    int f = blockIdx.x * blockDim.x + threadIdx.x;
    if (f == 0) { g_acc = 0.0; g_done = 0u; }
    if (f >= F) return;
    int a = faces[3 * f], b = faces[3 * f + 1], c = faces[3 * f + 2];
    store_succ(edst, a, b, c);
    store_succ(edst, b, c, a);
    store_succ(edst, c, a, b);
}

// ---------------------------------------------------------------------------
// K3: fused loss. One thread per vertex, BPT batches per thread.
// Neighbor list d[] from the sorted CSR edge_dst segment (coalesced); ring
// order walks g_succ; d[0] is the minimal neighbor so the coalescing
// rotation is free. deg-5: slot 5 duplicates n[0] so the wrap cross term
// vanishes. ||n/||n|||| == 1 so the un renormalization is dropped
// (validated R12). Last block (ticket) writes the scalar.
// ---------------------------------------------------------------------------
__global__ void __launch_bounds__(128)
k_loss(const int* __restrict__ edst, const float* __restrict__ target,
       float* __restrict__ out, unsigned int nblocks) {
    int vtx = blockIdx.x * blockDim.x + threadIdx.x;
    float local = 0.0f;
    if (vtx < NV) {
        int off = csr_off(vtx);
        int cnt = csr_deg(vtx);
        int d[6], s[6];
        #pragma unroll
        for (int i = 0; i < 6; i++) {
            // off+5 <= E-1 even for the last vertex (off(NV-1)+6 == E)
            d[i] = edst[off + i];
            s[i] = g_succ[off + i];
        }
        // walk the ring: start at the minimal neighbor d[0]
        int n[6];
        n[0] = d[0];
        int nxt = s[0];
        #pragma unroll
        for (int k = 1; k < 6; k++) {
            n[k] = nxt;
            int nn_ = nxt;
            #pragma unroll
            for (int i = 0; i < 6; i++)
                if (i < cnt && d[i] == nxt) nn_ = s[i];
            nxt = nn_;
        }
        if (cnt == 5) n[5] = n[0];       // duplicated: wrap cross term = 0

        float invd = 1.0f / (float)cnt;
        const float inv3 = 1.0f / 3.0f;

        #pragma unroll
        for (int bb = 0; bb < BPT; bb++) {
            int b = blockIdx.y * BPT + bb;
            const float4* vb = g_v4 + (size_t)b * NV;

            float4 p[6];
            #pragma unroll
            for (int i = 0; i < 6; i++) p[i] = __ldg(vb + n[i]);
            float4 pv = __ldg(vb + vtx);

            // ring-ordered cross sum: vn = sum_j p_j x p_{(j+1)%6}
            float nx = 0.f, ny = 0.f, nz = 0.f;
            #pragma unroll
            for (int j = 0; j < 6; j++) {
                const float4 a = p[j];
                const float4 c = p[(j + 1) % 6];
                nx += a.y * c.z - a.z * c.y;
                ny += a.z * c.x - a.x * c.z;
                nz += a.x * c.y - a.y * c.x;
            }
            // neighbor sum (subtract the duplicated n0 if deg==5)
            float sx = 0.f, sy = 0.f, sz = 0.f;
            #pragma unroll
            for (int j = 0; j < 6; j++) { sx += p[j].x; sy += p[j].y; sz += p[j].z; }
            if (cnt == 5) { sx -= p[0].x; sy -= p[0].y; sz -= p[0].z; }

            const float* t = target + (size_t)b * 9 * NV + vtx;
            // position loss (streamed target reads: evict-first)
            float dx = pv.x - __ldcs(t);
            float dy = pv.y - __ldcs(t + (size_t)NV);
            float dz = pv.z - __ldcs(t + 2 * (size_t)NV);
            float lpos = dx * dx + dy * dy + dz * dz;
            // normal cosine loss: ||u|| == 1 by construction
            float nn  = sqrtf(nx * nx + ny * ny + nz * nz);
            float inv = 1.0f / fmaxf(nn, 1e-12f);
            float ux = nx * inv, uy = ny * inv, uz = nz * inv;
            float tx = __ldcs(t + 3 * (size_t)NV);
            float ty = __ldcs(t + 4 * (size_t)NV);
            float tz = __ldcs(t + 5 * (size_t)NV);
            float tn = sqrtf(tx * tx + ty * ty + tz * tz);
            float cosv = (ux * tx + uy * ty + uz * tz) / fmaxf(tn, 1e-8f);
            // Laplacian loss
            float dlx = (pv.x - sx * invd) - __ldcs(t + 6 * (size_t)NV);
            float dly = (pv.y - sy * invd) - __ldcs(t + 7 * (size_t)NV);
            float dlz = (pv.z - sz * invd) - __ldcs(t + 8 * (size_t)NV);
            float llap = dlx * dlx + dly * dly + dlz * dlz;

            local += (lpos + llap) * inv3 + (1.0f - cosv);
        }
    }

    // warp shuffle reduce, then cross-warp smem reduce, one atomic per block
    #pragma unroll
    for (int off2 = 16; off2 > 0; off2 >>= 1)
        local += __shfl_xor_sync(0xFFFFFFFFu, local, off2);
    __shared__ float shw[4];
    int wid = threadIdx.x >> 5;
    if ((threadIdx.x & 31) == 0) shw[wid] = local;
    __syncthreads();
    if (threadIdx.x == 0) {
        float s = shw[0] + shw[1] + shw[2] + shw[3];
        atomicAdd(&g_acc, (double)s);
        __threadfence();
        unsigned int ticket = atomicAdd(&g_done, 1u);
        if (ticket == nblocks - 1u) {
            out[0] = (float)(g_acc / ((double)BATCH * (double)NV));
        }
    }
}

extern "C" void kernel_launch(void* const* d_in, const int* in_sizes, int n_in,
                              void* d_out, int out_size) {
    const float* inputs = (const float*)d_in[0];
    const float* target = (const float*)d_in[1];
    const int*   faces  = (const int*)  d_in[2];
    const int*   edst   = (const int*)  d_in[4];
    int F = in_sizes[2] / 3;

    // Fork-join overlap: the succ-map build (atomic-free) runs concurrent
    // with k_build_v. One-time stream/event setup on the eager call.
    static cudaStream_t s_side = nullptr;
    static cudaEvent_t  s_fork = nullptr, s_join = nullptr;
    if (s_side == nullptr) {
        cudaStreamCreateWithFlags(&s_side, cudaStreamNonBlocking);
        cudaEventCreateWithFlags(&s_fork, cudaEventDisableTiming);
        cudaEventCreateWithFlags(&s_join, cudaEventDisableTiming);
    }
    cudaStream_t main_s = 0;

    dim3 blk256(256);

    // fork
    cudaEventRecord(s_fork, main_s);
    cudaStreamWaitEvent(s_side, s_fork, 0);

    // side stream: build ring-successor map (no atomics, 2xLDG.128 scans)
    k_ring<<<(F + 255) / 256, blk256, 0, s_side>>>(faces, edst, F);
    cudaEventRecord(s_join, s_side);

    // main stream: vertex build, concurrent with the side chain
    k_build_v<<<dim3((YX + 2 + 255) / 256, BATCH), blk256, 0, main_s>>>(inputs);

    // join, then fused loss
    cudaStreamWaitEvent(main_s, s_join, 0);
    dim3 lgrid((NV + 127) / 128, BATCH / BPT);
    unsigned int nblocks = lgrid.x * lgrid.y;
    k_loss<<<lgrid, 128, 0, main_s>>>(edst, target, (float*)d_out, nblocks);
}